// round 4
// baseline (speedup 1.0000x reference)
#include <cuda_runtime.h>
#include <math.h>
#include <stdint.h>

// Problem constants
#define BBATCH 32
#define SFULL  201
#define SL     200
#define HDIM   512
#define EDIM   512
#define VDIM   32000
#define MROWS  (BBATCH * SL)   // 6400
#define NEGBIG -1e30f

// ---------------- scratch (device globals; no allocation allowed) ----------------
__device__ float g_hidden[MROWS * HDIM];
__device__ float g_head  [MROWS * HDIM];
__device__ float g_tail  [MROWS * HDIM];
__device__ float g_depend[MROWS * HDIM];
__device__ float g_gbuf  [MROWS * HDIM];
__device__ float g_enc   [MROWS * HDIM];
__device__ float g_m1    [MROWS * HDIM];
__device__ float g_rowmask[MROWS];
__device__ float g_pool  [MROWS];
__device__ int   g_gidx  [MROWS];
__device__ int   g_tidx  [MROWS];

// ---------------- prep: cas_len -> rowmask, gather indices ----------------
__global__ void prep_kernel(const int* __restrict__ cas, const int* __restrict__ tii) {
    int b = blockIdx.x;
    int tid = threadIdx.x;
    __shared__ int red[256];
    int cnt = 0;
    for (int i = tid; i < SL; i += 256) cnt += (cas[b * SFULL + i] != 0);
    red[tid] = cnt;
    __syncthreads();
    for (int s = 128; s > 0; s >>= 1) {
        if (tid < s) red[tid] += red[tid + s];
        __syncthreads();
    }
    int len = red[0];
    for (int i = tid; i < SL; i += 256) {
        int r = b * SL + i;
        g_rowmask[r] = (i < len) ? 1.0f : 0.0f;
        g_gidx[r] = cas[b * SFULL + i];
        g_tidx[r] = tii[b * SFULL + i];
    }
}

// ---------------- generic SGEMM: C[M,N] = epilogue(A[M,K] @ B[K,N]) ----------------
// Tiles: 128x128x8, 256 threads, 8x8 per thread (split 2x(4) rows / 2x(4) cols).
#define BM 128
#define BN 128
#define BK 8

#define EPI_BIAS          0   // C = acc + bias
#define EPI_BIAS_ELU      1   // C = elu(acc + bias)
#define EPI_BIAS_ELU_MASK 2   // C = elu(acc + bias) * rowvec[row]
#define EPI_ACC           3   // C += acc                (bias ignored)
#define EPI_BIAS_ELU_MUL  4   // C = C * elu(acc + bias)

__device__ __forceinline__ float elu_f(float x) { return x > 0.0f ? x : expm1f(x); }

template <int EPI, bool GATHER, bool ROWSCALE>
__launch_bounds__(256, 2)
__global__ void sgemm_kernel(const float* __restrict__ A, const float* __restrict__ Bm,
                             float* __restrict__ C, const float* __restrict__ bias,
                             const int* __restrict__ gidx, const float* __restrict__ rowvec,
                             int M, int N, int K) {
    __shared__ __align__(16) float As[BK][BM + 4];
    __shared__ __align__(16) float Bs[BK][BN];

    const int tid = threadIdx.x;
    const int bm = blockIdx.y * BM;
    const int bn = blockIdx.x * BN;

    // A load: 128 rows x 8 cols -> one float4 per thread
    const int arow = tid >> 1;
    const int acol = (tid & 1) * 4;
    const int grow = bm + arow;
    const float* Aptr = GATHER ? (A + (size_t)gidx[grow] * K) : (A + (size_t)grow * K);
    const float rscale = ROWSCALE ? rowvec[grow] : 1.0f;

    // B load: 8 rows x 128 cols -> one float4 per thread
    const int brow = tid >> 5;
    const int bcol = (tid & 31) * 4;

    const int tx = tid & 15;
    const int ty = tid >> 4;

    float acc[8][8];
#pragma unroll
    for (int i = 0; i < 8; i++)
#pragma unroll
        for (int j = 0; j < 8; j++) acc[i][j] = 0.0f;

    for (int kt = 0; kt < K; kt += BK) {
        float4 av = *(const float4*)(Aptr + kt + acol);
        if (ROWSCALE) { av.x *= rscale; av.y *= rscale; av.z *= rscale; av.w *= rscale; }
        As[acol + 0][arow] = av.x;
        As[acol + 1][arow] = av.y;
        As[acol + 2][arow] = av.z;
        As[acol + 3][arow] = av.w;
        float4 bv = *(const float4*)(Bm + (size_t)(kt + brow) * N + bn + bcol);
        *(float4*)&Bs[brow][bcol] = bv;
        __syncthreads();

#pragma unroll
        for (int kk = 0; kk < BK; kk++) {
            float a[8], bf[8];
            *(float4*)&a[0]  = *(const float4*)&As[kk][ty * 4];
            *(float4*)&a[4]  = *(const float4*)&As[kk][64 + ty * 4];
            *(float4*)&bf[0] = *(const float4*)&Bs[kk][tx * 4];
            *(float4*)&bf[4] = *(const float4*)&Bs[kk][64 + tx * 4];
#pragma unroll
            for (int i = 0; i < 8; i++)
#pragma unroll
                for (int j = 0; j < 8; j++) acc[i][j] = fmaf(a[i], bf[j], acc[i][j]);
        }
        __syncthreads();
    }

    // epilogue
#pragma unroll
    for (int ri = 0; ri < 2; ri++) {
#pragma unroll
        for (int ii = 0; ii < 4; ii++) {
            const int row = bm + ri * 64 + ty * 4 + ii;
            float mask = 1.0f;
            if (EPI == EPI_BIAS_ELU_MASK) mask = rowvec[row];
#pragma unroll
            for (int ci = 0; ci < 2; ci++) {
                const int col0 = bn + ci * 64 + tx * 4;
                float* cp = C + (size_t)row * N + col0;
                float4 v;
                float* vp = (float*)&v;
#pragma unroll
                for (int q = 0; q < 4; q++) {
                    float x = acc[ri * 4 + ii][ci * 4 + q];
                    if (EPI != EPI_ACC) x += bias[col0 + q];
                    if (EPI == EPI_BIAS_ELU || EPI == EPI_BIAS_ELU_MASK || EPI == EPI_BIAS_ELU_MUL)
                        x = elu_f(x);
                    if (EPI == EPI_BIAS_ELU_MASK) x *= mask;
                    vp[q] = x;
                }
                if (EPI == EPI_ACC) {
                    float4 old = *(float4*)cp;
                    v.x += old.x; v.y += old.y; v.z += old.z; v.w += old.w;
                } else if (EPI == EPI_BIAS_ELU_MUL) {
                    float4 old = *(float4*)cp;
                    v.x *= old.x; v.y *= old.y; v.z *= old.z; v.w *= old.w;
                }
                *(float4*)cp = v;
            }
        }
    }
}

// ---------------- fused attention: logits row -> masked softmax -> depend ----------------
// grid (SL, B), 256 threads. Causal: only j < i contribute.
__global__ void attn_kernel() {
    const int i = blockIdx.x;
    const int b = blockIdx.y;
    const int tid = threadIdx.x;
    const int lane = tid & 31;
    const int warp = tid >> 5;
    const int r = b * SL + i;

    __shared__ float sh_head[HDIM];
    __shared__ float sp[SL];
    __shared__ float rbuf[256];

    for (int k = tid; k < HDIM; k += 256) sh_head[k] = g_head[(size_t)r * HDIM + k];
    for (int j = tid; j < SL; j += 256) sp[j] = -3e38f;
    __syncthreads();

    // logits for j < i (valid columns only)
    for (int j = warp; j < i; j += 8) {
        const float* tr = g_tail + (size_t)(b * SL + j) * HDIM;
        float s = 0.0f;
        for (int k = lane; k < HDIM; k += 32) s = fmaf(sh_head[k], tr[k], s);
#pragma unroll
        for (int o = 16; o > 0; o >>= 1) s += __shfl_xor_sync(0xffffffff, s, o);
        if (lane == 0 && g_rowmask[b * SL + j] > 0.5f) sp[j] = s;
    }
    __syncthreads();

    // masked softmax over sp
    float v = (tid < SL) ? sp[tid] : -3e38f;
    rbuf[tid] = v;
    __syncthreads();
    for (int s = 128; s > 0; s >>= 1) {
        if (tid < s) rbuf[tid] = fmaxf(rbuf[tid], rbuf[tid + s]);
        __syncthreads();
    }
    const float m = rbuf[0];
    __syncthreads();
    float e = 0.0f;
    if (tid < SL && sp[tid] > -1e37f) e = expf(sp[tid] - m);
    rbuf[tid] = e;
    __syncthreads();
    for (int s = 128; s > 0; s >>= 1) {
        if (tid < s) rbuf[tid] += rbuf[tid + s];
        __syncthreads();
    }
    const float ssum = rbuf[0];
    __syncthreads();
    if (tid < SL) sp[tid] = (ssum > 0.0f) ? e / ssum : 0.0f;
    __syncthreads();

    // depend[r, :] = sum_j sp[j] * hidden[b*SL+j, :]
    float a0 = 0.0f, a1 = 0.0f;
    for (int j = 0; j < i; j++) {
        const float s = sp[j];
        if (s != 0.0f) {
            const float* hr = g_hidden + (size_t)(b * SL + j) * HDIM;
            a0 = fmaf(s, hr[tid], a0);
            a1 = fmaf(s, hr[tid + 256], a1);
        }
    }
    g_depend[(size_t)r * HDIM + tid]       = a0;
    g_depend[(size_t)r * HDIM + tid + 256] = a1;
}

// ---------------- gate blend: enc = (sig(gbuf)*hidden + (1-sig)*depend) * mask ----------------
__global__ void enc_kernel() {
    const int idx = blockIdx.x * 256 + threadIdx.x;
    const int r = idx >> 9;  // /HDIM
    const float g = 1.0f / (1.0f + expf(-g_gbuf[idx]));
    g_enc[idx] = (g * g_hidden[idx] + (1.0f - g) * g_depend[idx]) * g_rowmask[r];
}

// ---------------- map2 + pool softmax (per batch) ----------------
__global__ void pool_kernel(const float* __restrict__ wm2, const float* __restrict__ bm2) {
    const int b = blockIdx.x;
    const int tid = threadIdx.x;
    const int lane = tid & 31;
    const int warp = tid >> 5;

    __shared__ float sm2[SL];
    __shared__ float rbuf[256];

    for (int i = warp; i < SL; i += 8) {
        const float* mr = g_m1 + (size_t)(b * SL + i) * HDIM;
        float s = 0.0f;
        for (int k = lane; k < HDIM; k += 32) s = fmaf(mr[k], wm2[k], s);
#pragma unroll
        for (int o = 16; o > 0; o >>= 1) s += __shfl_xor_sync(0xffffffff, s, o);
        if (lane == 0) sm2[i] = s + bm2[0];
    }
    __syncthreads();

    const bool valid = (tid < SL) && (g_rowmask[b * SL + tid] > 0.5f);
    float v = valid ? sm2[tid] : -3e38f;
    rbuf[tid] = v;
    __syncthreads();
    for (int s = 128; s > 0; s >>= 1) {
        if (tid < s) rbuf[tid] = fmaxf(rbuf[tid], rbuf[tid + s]);
        __syncthreads();
    }
    const float m = rbuf[0];
    __syncthreads();
    float e = valid ? expf(sm2[tid] - m) : 0.0f;
    rbuf[tid] = e;
    __syncthreads();
    for (int s = 128; s > 0; s >>= 1) {
        if (tid < s) rbuf[tid] += rbuf[tid + s];
        __syncthreads();
    }
    const float ssum = rbuf[0];
    if (tid < SL) g_pool[b * SL + tid] = (ssum > 0.0f) ? e / ssum : 0.0f;
}

// ---------------- launch ----------------
extern "C" void kernel_launch(void* const* d_in, const int* in_sizes, int n_in,
                              void* d_out, int out_size) {
    const int*   cas  = (const int*)d_in[0];
    const int*   tiiv = (const int*)d_in[1];
    const float* emb  = (const float*)d_in[2];
    const float* tl   = (const float*)d_in[3];
    const float* w1   = (const float*)d_in[4];
    const float* b1   = (const float*)d_in[5];
    const float* wh   = (const float*)d_in[6];
    const float* bh   = (const float*)d_in[7];
    const float* wt   = (const float*)d_in[8];
    const float* bt   = (const float*)d_in[9];
    const float* wg   = (const float*)d_in[10];
    const float* bg   = (const float*)d_in[11];
    const float* wm1  = (const float*)d_in[12];
    const float* bm1  = (const float*)d_in[13];
    const float* wti  = (const float*)d_in[14];
    const float* bti  = (const float*)d_in[15];
    const float* wm2  = (const float*)d_in[16];
    const float* bm2  = (const float*)d_in[17];
    const float* wout = (const float*)d_in[18];
    const float* bout = (const float*)d_in[19];
    float* out = (float*)d_out;

    float *hiddenP, *headP, *tailP, *dependP, *gbufP, *encP, *m1P, *rowmaskP, *poolP;
    int *gidxP, *tidxP;
    cudaGetSymbolAddress((void**)&hiddenP, g_hidden);
    cudaGetSymbolAddress((void**)&headP,   g_head);
    cudaGetSymbolAddress((void**)&tailP,   g_tail);
    cudaGetSymbolAddress((void**)&dependP, g_depend);
    cudaGetSymbolAddress((void**)&gbufP,   g_gbuf);
    cudaGetSymbolAddress((void**)&encP,    g_enc);
    cudaGetSymbolAddress((void**)&m1P,     g_m1);
    cudaGetSymbolAddress((void**)&rowmaskP,g_rowmask);
    cudaGetSymbolAddress((void**)&poolP,   g_pool);
    cudaGetSymbolAddress((void**)&gidxP,   g_gidx);
    cudaGetSymbolAddress((void**)&tidxP,   g_tidx);

    prep_kernel<<<BBATCH, 256>>>(cas, tiiv);

    dim3 gH(HDIM / BN, MROWS / BM);   // (4, 50)
    dim3 gV(VDIM / BN, MROWS / BM);   // (250, 50)

    // hidden = elu(gather(emb) @ w1 + b1) * rowmask
    sgemm_kernel<EPI_BIAS_ELU_MASK, true, false><<<gH, 256>>>(
        emb, w1, hiddenP, b1, gidxP, rowmaskP, MROWS, HDIM, EDIM);
    // head / tail
    sgemm_kernel<EPI_BIAS, false, false><<<gH, 256>>>(
        hiddenP, wh, headP, bh, nullptr, nullptr, MROWS, HDIM, HDIM);
    sgemm_kernel<EPI_BIAS, false, false><<<gH, 256>>>(
        hiddenP, wt, tailP, bt, nullptr, nullptr, MROWS, HDIM, HDIM);

    // attention -> depend
    attn_kernel<<<dim3(SL, BBATCH), 256>>>();

    // gate pre-activation: gbuf = hidden@wg[:H] + bg ; gbuf += depend@wg[H:]
    sgemm_kernel<EPI_BIAS, false, false><<<gH, 256>>>(
        hiddenP, wg, gbufP, bg, nullptr, nullptr, MROWS, HDIM, HDIM);
    sgemm_kernel<EPI_ACC, false, false><<<gH, 256>>>(
        dependP, wg + (size_t)HDIM * HDIM, gbufP, nullptr, nullptr, nullptr, MROWS, HDIM, HDIM);

    // enc blend
    enc_kernel<<<(MROWS * HDIM) / 256, 256>>>();

    // m1 = elu(enc@wm1 + bm1); m1 *= elu(gather(time_lambda)@wti + bti)
    sgemm_kernel<EPI_BIAS_ELU, false, false><<<gH, 256>>>(
        encP, wm1, m1P, bm1, nullptr, nullptr, MROWS, HDIM, HDIM);
    sgemm_kernel<EPI_BIAS_ELU_MUL, true, false><<<gH, 256>>>(
        tl, wti, m1P, bti, tidxP, nullptr, MROWS, HDIM, HDIM);

    // pool softmax over sequence
    pool_kernel<<<BBATCH, 256>>>(wm2, bm2);

    // logits_out = (pool * enc) @ wout + bout
    sgemm_kernel<EPI_BIAS, false, true><<<gV, 256>>>(
        encP, wout, out, bout, nullptr, poolP, MROWS, VDIM, HDIM);
}

// round 6
// speedup vs baseline: 1.4935x; 1.4935x over previous
#include <cuda_runtime.h>
#include <cuda_bf16.h>
#include <math.h>
#include <stdint.h>

// Problem constants
#define BBATCH 32
#define SFULL  201
#define SL     200
#define HDIM   512
#define EDIM   512
#define VDIM   32000
#define MROWS  (BBATCH * SL)   // 6400
#define NEGBIG -1e30f

// ---------------- scratch (device globals; no allocation allowed) ----------------
__device__ float g_hidden[MROWS * HDIM];
__device__ float g_head  [MROWS * HDIM];
__device__ float g_tail  [MROWS * HDIM];
__device__ float g_depend[MROWS * HDIM];
__device__ float g_gbuf  [MROWS * HDIM];
__device__ float g_enc   [MROWS * HDIM];
__device__ float g_m1    [MROWS * HDIM];
__device__ float g_rowmask[MROWS];
__device__ float g_pool  [MROWS];
__device__ int   g_gidx  [MROWS];
__device__ int   g_tidx  [MROWS];

// split-bf16 operands for the warp-MMA output GEMM
__device__ __nv_bfloat16 g_Ahi[MROWS * HDIM];
__device__ __nv_bfloat16 g_Alo[MROWS * HDIM];
__device__ __nv_bfloat16 g_Bhi[(size_t)VDIM * HDIM];  // wout transposed [V, H]
__device__ __nv_bfloat16 g_Blo[(size_t)VDIM * HDIM];

// ---------------- base-PTX helpers (no sm_103a-only features!) ----------------
__device__ __forceinline__ uint32_t smem_u32(const void* p) {
    uint32_t a;
    asm("{ .reg .u64 t; cvta.to.shared.u64 t, %1; cvt.u32.u64 %0, t; }" : "=r"(a) : "l"(p));
    return a;
}

#define CP_ASYNC16(dst, src) \
    asm volatile("cp.async.cg.shared.global [%0], [%1], 16;" :: "r"(dst), "l"(src))
#define CP_COMMIT() asm volatile("cp.async.commit_group;" ::: "memory")
#define CP_WAIT1()  asm volatile("cp.async.wait_group 1;" ::: "memory")

#define LDSM4(r, addr)                                                        \
    asm volatile("ldmatrix.sync.aligned.m8n8.x4.shared.b16 {%0,%1,%2,%3}, [%4];" \
                 : "=r"((r)[0]), "=r"((r)[1]), "=r"((r)[2]), "=r"((r)[3])     \
                 : "r"(addr))

#define MMA_BF16(d, a, b0, b1)                                                \
    asm volatile("mma.sync.aligned.m16n8k16.row.col.f32.bf16.bf16.f32 "       \
                 "{%0,%1,%2,%3}, {%4,%5,%6,%7}, {%8,%9}, {%0,%1,%2,%3};"      \
                 : "+f"((d)[0]), "+f"((d)[1]), "+f"((d)[2]), "+f"((d)[3])     \
                 : "r"((a)[0]), "r"((a)[1]), "r"((a)[2]), "r"((a)[3]),        \
                   "r"(b0), "r"(b1))

// ---------------- prep: cas_len -> rowmask, gather indices ----------------
__global__ void prep_kernel(const int* __restrict__ cas, const int* __restrict__ tii) {
    int b = blockIdx.x;
    int tid = threadIdx.x;
    __shared__ int red[256];
    int cnt = 0;
    for (int i = tid; i < SL; i += 256) cnt += (cas[b * SFULL + i] != 0);
    red[tid] = cnt;
    __syncthreads();
    for (int s = 128; s > 0; s >>= 1) {
        if (tid < s) red[tid] += red[tid + s];
        __syncthreads();
    }
    int len = red[0];
    for (int i = tid; i < SL; i += 256) {
        int r = b * SL + i;
        g_rowmask[r] = (i < len) ? 1.0f : 0.0f;
        g_gidx[r] = cas[b * SFULL + i];
        g_tidx[r] = tii[b * SFULL + i];
    }
}

// ---------------- generic fp32 SGEMM (H-dim stages; validated in R3) ----------------
#define BM 128
#define BN 128
#define BK 8

#define EPI_BIAS          0
#define EPI_BIAS_ELU      1
#define EPI_BIAS_ELU_MASK 2
#define EPI_ACC           3
#define EPI_BIAS_ELU_MUL  4

__device__ __forceinline__ float elu_f(float x) { return x > 0.0f ? x : expm1f(x); }

template <int EPI, bool GATHER, bool ROWSCALE>
__launch_bounds__(256, 2)
__global__ void sgemm_kernel(const float* __restrict__ A, const float* __restrict__ Bm,
                             float* __restrict__ C, const float* __restrict__ bias,
                             const int* __restrict__ gidx, const float* __restrict__ rowvec,
                             int M, int N, int K) {
    __shared__ __align__(16) float As[BK][BM + 4];
    __shared__ __align__(16) float Bs[BK][BN];

    const int tid = threadIdx.x;
    const int bm = blockIdx.y * BM;
    const int bn = blockIdx.x * BN;

    const int arow = tid >> 1;
    const int acol = (tid & 1) * 4;
    const int grow = bm + arow;
    const float* Aptr = GATHER ? (A + (size_t)gidx[grow] * K) : (A + (size_t)grow * K);
    const float rscale = ROWSCALE ? rowvec[grow] : 1.0f;

    const int brow = tid >> 5;
    const int bcol = (tid & 31) * 4;

    const int tx = tid & 15;
    const int ty = tid >> 4;

    float acc[8][8];
#pragma unroll
    for (int i = 0; i < 8; i++)
#pragma unroll
        for (int j = 0; j < 8; j++) acc[i][j] = 0.0f;

    for (int kt = 0; kt < K; kt += BK) {
        float4 av = *(const float4*)(Aptr + kt + acol);
        if (ROWSCALE) { av.x *= rscale; av.y *= rscale; av.z *= rscale; av.w *= rscale; }
        As[acol + 0][arow] = av.x;
        As[acol + 1][arow] = av.y;
        As[acol + 2][arow] = av.z;
        As[acol + 3][arow] = av.w;
        float4 bv = *(const float4*)(Bm + (size_t)(kt + brow) * N + bn + bcol);
        *(float4*)&Bs[brow][bcol] = bv;
        __syncthreads();

#pragma unroll
        for (int kk = 0; kk < BK; kk++) {
            float a[8], bf[8];
            *(float4*)&a[0]  = *(const float4*)&As[kk][ty * 4];
            *(float4*)&a[4]  = *(const float4*)&As[kk][64 + ty * 4];
            *(float4*)&bf[0] = *(const float4*)&Bs[kk][tx * 4];
            *(float4*)&bf[4] = *(const float4*)&Bs[kk][64 + tx * 4];
#pragma unroll
            for (int i = 0; i < 8; i++)
#pragma unroll
                for (int j = 0; j < 8; j++) acc[i][j] = fmaf(a[i], bf[j], acc[i][j]);
        }
        __syncthreads();
    }

#pragma unroll
    for (int ri = 0; ri < 2; ri++) {
#pragma unroll
        for (int ii = 0; ii < 4; ii++) {
            const int row = bm + ri * 64 + ty * 4 + ii;
            float mask = 1.0f;
            if (EPI == EPI_BIAS_ELU_MASK) mask = rowvec[row];
#pragma unroll
            for (int ci = 0; ci < 2; ci++) {
                const int col0 = bn + ci * 64 + tx * 4;
                float* cp = C + (size_t)row * N + col0;
                float4 v;
                float* vp = (float*)&v;
#pragma unroll
                for (int q = 0; q < 4; q++) {
                    float x = acc[ri * 4 + ii][ci * 4 + q];
                    if (EPI != EPI_ACC) x += bias[col0 + q];
                    if (EPI == EPI_BIAS_ELU || EPI == EPI_BIAS_ELU_MASK || EPI == EPI_BIAS_ELU_MUL)
                        x = elu_f(x);
                    if (EPI == EPI_BIAS_ELU_MASK) x *= mask;
                    vp[q] = x;
                }
                if (EPI == EPI_ACC) {
                    float4 old = *(float4*)cp;
                    v.x += old.x; v.y += old.y; v.z += old.z; v.w += old.w;
                } else if (EPI == EPI_BIAS_ELU_MUL) {
                    float4 old = *(float4*)cp;
                    v.x *= old.x; v.y *= old.y; v.z *= old.z; v.w *= old.w;
                }
                *(float4*)cp = v;
            }
        }
    }
}

// ---------------- fused attention ----------------
__global__ void attn_kernel() {
    const int i = blockIdx.x;
    const int b = blockIdx.y;
    const int tid = threadIdx.x;
    const int lane = tid & 31;
    const int warp = tid >> 5;
    const int r = b * SL + i;

    __shared__ float sh_head[HDIM];
    __shared__ float sp[SL];
    __shared__ float rbuf[256];

    for (int k = tid; k < HDIM; k += 256) sh_head[k] = g_head[(size_t)r * HDIM + k];
    for (int j = tid; j < SL; j += 256) sp[j] = -3e38f;
    __syncthreads();

    for (int j = warp; j < i; j += 8) {
        const float* tr = g_tail + (size_t)(b * SL + j) * HDIM;
        float s = 0.0f;
        for (int k = lane; k < HDIM; k += 32) s = fmaf(sh_head[k], tr[k], s);
#pragma unroll
        for (int o = 16; o > 0; o >>= 1) s += __shfl_xor_sync(0xffffffff, s, o);
        if (lane == 0 && g_rowmask[b * SL + j] > 0.5f) sp[j] = s;
    }
    __syncthreads();

    float v = (tid < SL) ? sp[tid] : -3e38f;
    rbuf[tid] = v;
    __syncthreads();
    for (int s = 128; s > 0; s >>= 1) {
        if (tid < s) rbuf[tid] = fmaxf(rbuf[tid], rbuf[tid + s]);
        __syncthreads();
    }
    const float m = rbuf[0];
    __syncthreads();
    float e = 0.0f;
    if (tid < SL && sp[tid] > -1e37f) e = expf(sp[tid] - m);
    rbuf[tid] = e;
    __syncthreads();
    for (int s = 128; s > 0; s >>= 1) {
        if (tid < s) rbuf[tid] += rbuf[tid + s];
        __syncthreads();
    }
    const float ssum = rbuf[0];
    __syncthreads();
    if (tid < SL) sp[tid] = (ssum > 0.0f) ? e / ssum : 0.0f;
    __syncthreads();

    float a0 = 0.0f, a1 = 0.0f;
    for (int j = 0; j < i; j++) {
        const float s = sp[j];
        if (s != 0.0f) {
            const float* hr = g_hidden + (size_t)(b * SL + j) * HDIM;
            a0 = fmaf(s, hr[tid], a0);
            a1 = fmaf(s, hr[tid + 256], a1);
        }
    }
    g_depend[(size_t)r * HDIM + tid]       = a0;
    g_depend[(size_t)r * HDIM + tid + 256] = a1;
}

// ---------------- gate blend ----------------
__global__ void enc_kernel() {
    const int idx = blockIdx.x * 256 + threadIdx.x;
    const int r = idx >> 9;
    const float g = 1.0f / (1.0f + expf(-g_gbuf[idx]));
    g_enc[idx] = (g * g_hidden[idx] + (1.0f - g) * g_depend[idx]) * g_rowmask[r];
}

// ---------------- map2 + pool softmax ----------------
__global__ void pool_kernel(const float* __restrict__ wm2, const float* __restrict__ bm2) {
    const int b = blockIdx.x;
    const int tid = threadIdx.x;
    const int lane = tid & 31;
    const int warp = tid >> 5;

    __shared__ float sm2[SL];
    __shared__ float rbuf[256];

    for (int i = warp; i < SL; i += 8) {
        const float* mr = g_m1 + (size_t)(b * SL + i) * HDIM;
        float s = 0.0f;
        for (int k = lane; k < HDIM; k += 32) s = fmaf(mr[k], wm2[k], s);
#pragma unroll
        for (int o = 16; o > 0; o >>= 1) s += __shfl_xor_sync(0xffffffff, s, o);
        if (lane == 0) sm2[i] = s + bm2[0];
    }
    __syncthreads();

    const bool valid = (tid < SL) && (g_rowmask[b * SL + tid] > 0.5f);
    float v = valid ? sm2[tid] : -3e38f;
    rbuf[tid] = v;
    __syncthreads();
    for (int s = 128; s > 0; s >>= 1) {
        if (tid < s) rbuf[tid] = fmaxf(rbuf[tid], rbuf[tid + s]);
        __syncthreads();
    }
    const float m = rbuf[0];
    __syncthreads();
    float e = valid ? expf(sm2[tid] - m) : 0.0f;
    rbuf[tid] = e;
    __syncthreads();
    for (int s = 128; s > 0; s >>= 1) {
        if (tid < s) rbuf[tid] += rbuf[tid + s];
        __syncthreads();
    }
    const float ssum = rbuf[0];
    if (tid < SL) g_pool[b * SL + tid] = (ssum > 0.0f) ? e / ssum : 0.0f;
}

// ---------------- split-precision conversions ----------------
// A = (pool * enc) -> bf16 hi/lo, [MROWS, HDIM]
__global__ void convA_kernel() {
    const int idx = blockIdx.x * 256 + threadIdx.x;
    const int row = idx >> 9;
    const float x = g_enc[idx] * g_pool[row];
    const __nv_bfloat16 hi = __float2bfloat16(x);
    g_Ahi[idx] = hi;
    g_Alo[idx] = __float2bfloat16(x - __bfloat162float(hi));
}

// wout [HDIM, VDIM] fp32 -> transposed bf16 hi/lo [VDIM, HDIM]
__global__ void convB_kernel(const float* __restrict__ w) {
    __shared__ float t[32][33];
    const int nt = blockIdx.x * 32;
    const int kt = blockIdx.y * 32;
    const int tx = threadIdx.x;
    const int ty = threadIdx.y;
#pragma unroll
    for (int i = 0; i < 32; i += 8)
        t[ty + i][tx] = w[(size_t)(kt + ty + i) * VDIM + nt + tx];
    __syncthreads();
#pragma unroll
    for (int i = 0; i < 32; i += 8) {
        const float x = t[tx][ty + i];
        const __nv_bfloat16 hi = __float2bfloat16(x);
        const size_t o = (size_t)(nt + ty + i) * HDIM + kt + tx;
        g_Bhi[o] = hi;
        g_Blo[o] = __float2bfloat16(x - __bfloat162float(hi));
    }
}

// ---------------- split-bf16 warp-MMA GEMM: out[M,V] = A @ Bt^T + bout ----------------
// Block 128x128, K stage = 16. 8 warps, warp tile 32x64 (4x2 warp grid).
// smem tile row = 32 bf16 (hi k0-7 | hi k8-15 | lo k0-7 | lo k8-15), 64B,
// 16B-chunk swizzle: c' = c ^ ((row>>1)&3)  -> conflict-free ldmatrix.
#define STAGES 3
#define STAGE_ELEMS (128 * 32)     // per matrix per stage (bf16)

__global__ __launch_bounds__(256, 1) void wout_mma_kernel(const float* __restrict__ bias,
                                                          float* __restrict__ out) {
    __shared__ __align__(16) __nv_bfloat16 sA[STAGES * STAGE_ELEMS];
    __shared__ __align__(16) __nv_bfloat16 sB[STAGES * STAGE_ELEMS];

    const int tid  = threadIdx.x;
    const int lane = tid & 31;
    const int wid  = tid >> 5;
    const int wm   = wid >> 1;        // 0..3  (m warp)
    const int wn   = wid & 1;         // 0..1  (n warp)
    const int bn   = blockIdx.x * 128;
    const int bm   = blockIdx.y * 128;

    const uint32_t sAaddr = smem_u32(sA);
    const uint32_t sBaddr = smem_u32(sB);

    float acc[2][8][4];
#pragma unroll
    for (int t = 0; t < 2; t++)
#pragma unroll
        for (int n = 0; n < 8; n++)
#pragma unroll
            for (int q = 0; q < 4; q++) acc[t][n][q] = 0.0f;

    // ---- stage loader: 1024 x 16B cp.async chunks (A: 512, B: 512) ----
    auto load_stage = [&](int stage, int kt) {
        const int kbase = kt * 16;
#pragma unroll
        for (int i = 0; i < 4; i++) {
            const int id   = tid + i * 256;       // 0..1023
            const int isB  = id >> 9;
            const int sub  = id & 511;
            const int half = sub & 1;             // k half (0: k0-7, 1: k8-15)
            const int r    = (sub >> 1) & 127;    // tile row
            const int hl   = (sub >> 8) & 1;      // 0 hi, 1 lo
            const int c    = hl * 2 + half;
            const __nv_bfloat16* gsrc;
            if (isB) gsrc = (hl ? g_Blo : g_Bhi) + (size_t)(bn + r) * HDIM + kbase + half * 8;
            else     gsrc = (hl ? g_Alo : g_Ahi) + (size_t)(bm + r) * HDIM + kbase + half * 8;
            const uint32_t dst = (isB ? sBaddr : sAaddr) +
                (uint32_t)(stage * STAGE_ELEMS + r * 32 + (c ^ ((r >> 1) & 3)) * 8) * 2;
            CP_ASYNC16(dst, gsrc);
        }
    };

    // prologue: stages 0,1
    load_stage(0, 0); CP_COMMIT();
    load_stage(1, 1); CP_COMMIT();

    // precompute per-warp ldmatrix row/col pieces
    const int a_m   = wm * 32 + (lane & 15);      // + t*16
    const int a_kg  = lane >> 4;                  // 0/1 k-halves
    const int b_n   = wn * 64 + (lane & 7) + ((lane >> 4) & 1) * 8;  // + np*16
    const int b_kg  = (lane >> 3) & 1;

    for (int kt = 0; kt < HDIM / 16; kt++) {
        const int s = kt % STAGES;
        CP_WAIT1();
        __syncthreads();

        const uint32_t baseA = sAaddr + (uint32_t)(s * STAGE_ELEMS) * 2;
        const uint32_t baseB = sBaddr + (uint32_t)(s * STAGE_ELEMS) * 2;

        uint32_t aHi[2][4], aLo[2][4];
#pragma unroll
        for (int t = 0; t < 2; t++) {
            const int r = a_m + t * 16;
            const uint32_t sw = (uint32_t)((r >> 1) & 3);
            LDSM4(aHi[t], baseA + (uint32_t)(r * 32 + ((a_kg       ^ sw)) * 8) * 2);
            LDSM4(aLo[t], baseA + (uint32_t)(r * 32 + (((2 + a_kg) ^ sw)) * 8) * 2);
        }

#pragma unroll
        for (int np = 0; np < 4; np++) {
            const int n = b_n + np * 16;
            const uint32_t sw = (uint32_t)((n >> 1) & 3);
            uint32_t bHi[4], bLo[4];
            LDSM4(bHi, baseB + (uint32_t)(n * 32 + ((b_kg       ^ sw)) * 8) * 2);
            LDSM4(bLo, baseB + (uint32_t)(n * 32 + (((2 + b_kg) ^ sw)) * 8) * 2);
#pragma unroll
            for (int t = 0; t < 2; t++) {
                MMA_BF16(acc[t][2 * np],     aHi[t], bHi[0], bHi[1]);
                MMA_BF16(acc[t][2 * np + 1], aHi[t], bHi[2], bHi[3]);
                MMA_BF16(acc[t][2 * np],     aHi[t], bLo[0], bLo[1]);
                MMA_BF16(acc[t][2 * np + 1], aHi[t], bLo[2], bLo[3]);
                MMA_BF16(acc[t][2 * np],     aLo[t], bHi[0], bHi[1]);
                MMA_BF16(acc[t][2 * np + 1], aLo[t], bHi[2], bHi[3]);
            }
        }

        __syncthreads();
        const int nk = kt + STAGES - 1;
        if (nk < HDIM / 16) load_stage(nk % STAGES, nk);
        CP_COMMIT();
    }

    // epilogue: fragment layout c0,c1 -> (row = lane>>2, cols 2(lane&3)+{0,1}); c2,c3 -> row+8
#pragma unroll
    for (int t = 0; t < 2; t++) {
        const int row0 = bm + wm * 32 + t * 16 + (lane >> 2);
#pragma unroll
        for (int ni = 0; ni < 8; ni++) {
            const int col = bn + wn * 64 + ni * 8 + (lane & 3) * 2;
            const float bx = bias[col], by = bias[col + 1];
            float2 v0 = make_float2(acc[t][ni][0] + bx, acc[t][ni][1] + by);
            float2 v1 = make_float2(acc[t][ni][2] + bx, acc[t][ni][3] + by);
            *(float2*)(out + (size_t)row0 * VDIM + col)       = v0;
            *(float2*)(out + (size_t)(row0 + 8) * VDIM + col) = v1;
        }
    }
}

// ---------------- launch ----------------
extern "C" void kernel_launch(void* const* d_in, const int* in_sizes, int n_in,
                              void* d_out, int out_size) {
    const int*   cas  = (const int*)d_in[0];
    const int*   tiiv = (const int*)d_in[1];
    const float* emb  = (const float*)d_in[2];
    const float* tl   = (const float*)d_in[3];
    const float* w1   = (const float*)d_in[4];
    const float* b1   = (const float*)d_in[5];
    const float* wh   = (const float*)d_in[6];
    const float* bh   = (const float*)d_in[7];
    const float* wt   = (const float*)d_in[8];
    const float* bt   = (const float*)d_in[9];
    const float* wg   = (const float*)d_in[10];
    const float* bg   = (const float*)d_in[11];
    const float* wm1  = (const float*)d_in[12];
    const float* bm1  = (const float*)d_in[13];
    const float* wti  = (const float*)d_in[14];
    const float* bti  = (const float*)d_in[15];
    const float* wm2  = (const float*)d_in[16];
    const float* bm2  = (const float*)d_in[17];
    const float* wout = (const float*)d_in[18];
    const float* bout = (const float*)d_in[19];
    float* out = (float*)d_out;

    float *hiddenP, *headP, *tailP, *dependP, *gbufP, *encP, *m1P, *rowmaskP, *poolP;
    int *gidxP, *tidxP;
    cudaGetSymbolAddress((void**)&hiddenP, g_hidden);
    cudaGetSymbolAddress((void**)&headP,   g_head);
    cudaGetSymbolAddress((void**)&tailP,   g_tail);
    cudaGetSymbolAddress((void**)&dependP, g_depend);
    cudaGetSymbolAddress((void**)&gbufP,   g_gbuf);
    cudaGetSymbolAddress((void**)&encP,    g_enc);
    cudaGetSymbolAddress((void**)&m1P,     g_m1);
    cudaGetSymbolAddress((void**)&rowmaskP,g_rowmask);
    cudaGetSymbolAddress((void**)&poolP,   g_pool);
    cudaGetSymbolAddress((void**)&gidxP,   g_gidx);
    cudaGetSymbolAddress((void**)&tidxP,   g_tidx);

    prep_kernel<<<BBATCH, 256>>>(cas, tiiv);

    dim3 gH(HDIM / BN, MROWS / BM);   // (4, 50)

    // hidden = elu(gather(emb) @ w1 + b1) * rowmask
    sgemm_kernel<EPI_BIAS_ELU_MASK, true, false><<<gH, 256>>>(
        emb, w1, hiddenP, b1, gidxP, rowmaskP, MROWS, HDIM, EDIM);
    // head / tail
    sgemm_kernel<EPI_BIAS, false, false><<<gH, 256>>>(
        hiddenP, wh, headP, bh, nullptr, nullptr, MROWS, HDIM, HDIM);
    sgemm_kernel<EPI_BIAS, false, false><<<gH, 256>>>(
        hiddenP, wt, tailP, bt, nullptr, nullptr, MROWS, HDIM, HDIM);

    // wout split/transpose (depends only on the input weight)
    convB_kernel<<<dim3(VDIM / 32, HDIM / 32), dim3(32, 8)>>>(wout);

    // attention -> depend
    attn_kernel<<<dim3(SL, BBATCH), 256>>>();

    // gate pre-activation
    sgemm_kernel<EPI_BIAS, false, false><<<gH, 256>>>(
        hiddenP, wg, gbufP, bg, nullptr, nullptr, MROWS, HDIM, HDIM);
    sgemm_kernel<EPI_ACC, false, false><<<gH, 256>>>(
        dependP, wg + (size_t)HDIM * HDIM, gbufP, nullptr, nullptr, nullptr, MROWS, HDIM, HDIM);

    // enc blend
    enc_kernel<<<(MROWS * HDIM) / 256, 256>>>();

    // m1 = elu(enc@wm1 + bm1); m1 *= elu(gather(time_lambda)@wti + bti)
    sgemm_kernel<EPI_BIAS_ELU, false, false><<<gH, 256>>>(
        encP, wm1, m1P, bm1, nullptr, nullptr, MROWS, HDIM, HDIM);
    sgemm_kernel<EPI_BIAS_ELU_MUL, true, false><<<gH, 256>>>(
        tl, wti, m1P, bti, tidxP, nullptr, MROWS, HDIM, HDIM);

    // pool softmax over sequence
    pool_kernel<<<BBATCH, 256>>>(wm2, bm2);

    // A = pool*enc -> bf16 hi/lo
    convA_kernel<<<(MROWS * HDIM) / 256, 256>>>();

    // logits_out = A @ wout^T (split bf16, warp MMA) + bout
    wout_mma_kernel<<<dim3(VDIM / 128, MROWS / 128), 256>>>(bout, out);
}

// round 8
// speedup vs baseline: 2.1438x; 1.4354x over previous
#include <cuda_runtime.h>
#include <cuda_bf16.h>
#include <math.h>
#include <stdint.h>

// Problem constants
#define BBATCH 32
#define SFULL  201
#define SL     200
#define HDIM   512
#define EDIM   512
#define VDIM   32000
#define TDIM   101
#define MROWS  (BBATCH * SL)   // 6400

// ---------------- scratch (device globals; no allocation allowed) ----------------
__device__ float g_hidden[MROWS * HDIM];
__device__ float g_head  [MROWS * HDIM];
__device__ float g_tail  [MROWS * HDIM];
__device__ float g_depend[MROWS * HDIM];
__device__ float g_gbuf  [MROWS * HDIM];
__device__ float g_enc   [MROWS * HDIM];
__device__ float g_m1    [MROWS * HDIM];
__device__ float g_rowmask[MROWS];
__device__ float g_pool  [MROWS];
__device__ int   g_gidx  [MROWS];
__device__ int   g_tidx  [MROWS];

// split-bf16 operand buffers
__device__ __nv_bfloat16 g_embHi[(size_t)VDIM * EDIM];
__device__ __nv_bfloat16 g_embLo[(size_t)VDIM * EDIM];
__device__ __nv_bfloat16 g_tlHi[TDIM * HDIM];
__device__ __nv_bfloat16 g_tlLo[TDIM * HDIM];
__device__ __nv_bfloat16 g_hidHi[MROWS * HDIM];
__device__ __nv_bfloat16 g_hidLo[MROWS * HDIM];
__device__ __nv_bfloat16 g_depHi[MROWS * HDIM];
__device__ __nv_bfloat16 g_depLo[MROWS * HDIM];
__device__ __nv_bfloat16 g_encHi[MROWS * HDIM];
__device__ __nv_bfloat16 g_encLo[MROWS * HDIM];
__device__ __nv_bfloat16 g_Ahi[MROWS * HDIM];
__device__ __nv_bfloat16 g_Alo[MROWS * HDIM];
__device__ __nv_bfloat16 g_Bhi[(size_t)VDIM * HDIM];  // wout transposed [V, H]
__device__ __nv_bfloat16 g_Blo[(size_t)VDIM * HDIM];
// 7 transposed/split weights [512,512] each: w1, wh, wt, wg1, wg2, wm1, wti
#define WSLOT (HDIM * HDIM)
__device__ __nv_bfloat16 g_wTHi[7 * WSLOT];
__device__ __nv_bfloat16 g_wTLo[7 * WSLOT];

// ---------------- base-PTX helpers (target is plain sm_103: no tcgen05!) --------
__device__ __forceinline__ uint32_t smem_u32(const void* p) {
    uint32_t a;
    asm("{ .reg .u64 t; cvta.to.shared.u64 t, %1; cvt.u32.u64 %0, t; }" : "=r"(a) : "l"(p));
    return a;
}

#define CP_ASYNC16(dst, src) \
    asm volatile("cp.async.cg.shared.global [%0], [%1], 16;" :: "r"(dst), "l"(src))
#define CP_COMMIT() asm volatile("cp.async.commit_group;" ::: "memory")
#define CP_WAIT1()  asm volatile("cp.async.wait_group 1;" ::: "memory")

#define LDSM4(r, addr)                                                        \
    asm volatile("ldmatrix.sync.aligned.m8n8.x4.shared.b16 {%0,%1,%2,%3}, [%4];" \
                 : "=r"((r)[0]), "=r"((r)[1]), "=r"((r)[2]), "=r"((r)[3])     \
                 : "r"(addr))

#define MMA_BF16(d, a, b0, b1)                                                \
    asm volatile("mma.sync.aligned.m16n8k16.row.col.f32.bf16.bf16.f32 "       \
                 "{%0,%1,%2,%3}, {%4,%5,%6,%7}, {%8,%9}, {%0,%1,%2,%3};"      \
                 : "+f"((d)[0]), "+f"((d)[1]), "+f"((d)[2]), "+f"((d)[3])     \
                 : "r"((a)[0]), "r"((a)[1]), "r"((a)[2]), "r"((a)[3]),        \
                   "r"(b0), "r"(b1))

__device__ __forceinline__ float elu_f(float x) { return x > 0.0f ? x : expm1f(x); }

// ---------------- prep: cas_len -> rowmask, gather indices ----------------
__global__ void prep_kernel(const int* __restrict__ cas, const int* __restrict__ tii) {
    int b = blockIdx.x;
    int tid = threadIdx.x;
    __shared__ int red[256];
    int cnt = 0;
    for (int i = tid; i < SL; i += 256) cnt += (cas[b * SFULL + i] != 0);
    red[tid] = cnt;
    __syncthreads();
    for (int s = 128; s > 0; s >>= 1) {
        if (tid < s) red[tid] += red[tid + s];
        __syncthreads();
    }
    int len = red[0];
    for (int i = tid; i < SL; i += 256) {
        int r = b * SL + i;
        g_rowmask[r] = (i < len) ? 1.0f : 0.0f;
        g_gidx[r] = cas[b * SFULL + i];
        g_tidx[r] = tii[b * SFULL + i];
    }
}

// ---------------- elementwise fp32 -> bf16 hi/lo split ----------------
__global__ void split_kernel(const float* __restrict__ src, __nv_bfloat16* __restrict__ hi,
                             __nv_bfloat16* __restrict__ lo, int n) {
    const int idx = blockIdx.x * 256 + threadIdx.x;
    if (idx >= n) return;
    const float x = src[idx];
    const __nv_bfloat16 h = __float2bfloat16(x);
    hi[idx] = h;
    lo[idx] = __float2bfloat16(x - __bfloat162float(h));
}

// ---------------- transpose + split: src [512, ncols] fp32 -> out [ncols, 512] ----------------
__global__ void convT_kernel(const float* __restrict__ w, int ncols,
                             __nv_bfloat16* __restrict__ hi, __nv_bfloat16* __restrict__ lo) {
    __shared__ float t[32][33];
    const int nt = blockIdx.x * 32;
    const int kt = blockIdx.y * 32;
    const int tx = threadIdx.x;
    const int ty = threadIdx.y;
#pragma unroll
    for (int i = 0; i < 32; i += 8)
        t[ty + i][tx] = w[(size_t)(kt + ty + i) * ncols + nt + tx];
    __syncthreads();
#pragma unroll
    for (int i = 0; i < 32; i += 8) {
        const float x = t[tx][ty + i];
        const __nv_bfloat16 h = __float2bfloat16(x);
        const size_t o = (size_t)(nt + ty + i) * HDIM + kt + tx;
        hi[o] = h;
        lo[o] = __float2bfloat16(x - __bfloat162float(h));
    }
}

// ---------------- unified split-bf16 HMMA GEMM ----------------
// C[M, N] = epilogue(A[M, 512] @ B^T  [B stored as [N, 512]]) ; K = 512.
// Block 128x128, 8 warps (4m x 2n), warp tile 32x64, 3-stage cp.async pipeline.
// smem row = 32 bf16 (hi k0-7 | hi k8-15 | lo k0-7 | lo k8-15), 16B-chunk
// swizzle c' = c ^ ((row>>1)&3) -> conflict-free ldmatrix (validated R5).
#define STAGES 3
#define STAGE_ELEMS (128 * 32)

#define HEPI_BIAS          0   // C = acc + bias
#define HEPI_ELU           1   // C = elu(acc + bias)
#define HEPI_ELU_MASK_SPLIT 2  // x = elu(acc+bias)*rowvec[row]; C = x; Chi/Clo = split(x)
#define HEPI_ACC           3   // C += acc
#define HEPI_ELU_MUL       4   // C *= elu(acc + bias)

template <int EPI, bool GATHER>
__global__ __launch_bounds__(256, 2)
void hmma_gemm(const __nv_bfloat16* __restrict__ Ahi, const __nv_bfloat16* __restrict__ Alo,
               const __nv_bfloat16* __restrict__ Bhi, const __nv_bfloat16* __restrict__ Blo,
               float* __restrict__ C, const float* __restrict__ bias,
               const int* __restrict__ gidx, const float* __restrict__ rowvec,
               __nv_bfloat16* __restrict__ Chi, __nv_bfloat16* __restrict__ Clo,
               int N) {
    __shared__ __align__(16) __nv_bfloat16 sA[STAGES * STAGE_ELEMS];
    __shared__ __align__(16) __nv_bfloat16 sB[STAGES * STAGE_ELEMS];

    const int tid  = threadIdx.x;
    const int lane = tid & 31;
    const int wid  = tid >> 5;
    const int wm   = wid >> 1;        // 0..3
    const int wn   = wid & 1;         // 0..1
    const int bn   = blockIdx.x * 128;
    const int bm   = blockIdx.y * 128;

    const uint32_t sAaddr = smem_u32(sA);
    const uint32_t sBaddr = smem_u32(sB);

    float acc[2][8][4];
#pragma unroll
    for (int t = 0; t < 2; t++)
#pragma unroll
        for (int n = 0; n < 8; n++)
#pragma unroll
            for (int q = 0; q < 4; q++) acc[t][n][q] = 0.0f;

    // stage loader: 1024 x 16B cp.async chunks (A: 512, B: 512)
    auto load_stage = [&](int stage, int kt) {
        const int kbase = kt * 16;
#pragma unroll
        for (int i = 0; i < 4; i++) {
            const int id   = tid + i * 256;       // 0..1023
            const int isB  = id >> 9;
            const int sub  = id & 511;
            const int half = sub & 1;             // k half (0: k0-7, 1: k8-15)
            const int r    = (sub >> 1) & 127;    // tile row
            const int hl   = (sub >> 8) & 1;      // 0 hi, 1 lo
            const int c    = hl * 2 + half;
            const __nv_bfloat16* gsrc;
            if (isB) {
                gsrc = (hl ? Blo : Bhi) + (size_t)(bn + r) * HDIM + kbase + half * 8;
            } else {
                const int ar = GATHER ? gidx[bm + r] : (bm + r);
                gsrc = (hl ? Alo : Ahi) + (size_t)ar * HDIM + kbase + half * 8;
            }
            const uint32_t dst = (isB ? sBaddr : sAaddr) +
                (uint32_t)(stage * STAGE_ELEMS + r * 32 + (c ^ ((r >> 1) & 3)) * 8) * 2;
            CP_ASYNC16(dst, gsrc);
        }
    };

    // prologue: stages 0,1
    load_stage(0, 0); CP_COMMIT();
    load_stage(1, 1); CP_COMMIT();

    const int a_m  = wm * 32 + (lane & 15);
    const int a_kg = lane >> 4;
    const int b_n  = wn * 64 + (lane & 7) + ((lane >> 4) & 1) * 8;
    const int b_kg = (lane >> 3) & 1;

    for (int kt = 0; kt < HDIM / 16; kt++) {
        const int s = kt % STAGES;
        CP_WAIT1();
        __syncthreads();   // all warps done with stage (kt-1); its slot is free

        // overlap: issue next stage's loads before computing this one
        if (kt + 2 < HDIM / 16) load_stage((kt + 2) % STAGES, kt + 2);
        CP_COMMIT();

        const uint32_t baseA = sAaddr + (uint32_t)(s * STAGE_ELEMS) * 2;
        const uint32_t baseB = sBaddr + (uint32_t)(s * STAGE_ELEMS) * 2;

        uint32_t aHi[2][4], aLo[2][4];
#pragma unroll
        for (int t = 0; t < 2; t++) {
            const int r = a_m + t * 16;
            const uint32_t sw = (uint32_t)((r >> 1) & 3);
            LDSM4(aHi[t], baseA + (uint32_t)(r * 32 + ((a_kg       ^ sw)) * 8) * 2);
            LDSM4(aLo[t], baseA + (uint32_t)(r * 32 + (((2 + a_kg) ^ sw)) * 8) * 2);
        }

#pragma unroll
        for (int np = 0; np < 4; np++) {
            const int n = b_n + np * 16;
            const uint32_t sw = (uint32_t)((n >> 1) & 3);
            uint32_t bHi[4], bLo[4];
            LDSM4(bHi, baseB + (uint32_t)(n * 32 + ((b_kg       ^ sw)) * 8) * 2);
            LDSM4(bLo, baseB + (uint32_t)(n * 32 + (((2 + b_kg) ^ sw)) * 8) * 2);
#pragma unroll
            for (int t = 0; t < 2; t++) {
                MMA_BF16(acc[t][2 * np],     aHi[t], bHi[0], bHi[1]);
                MMA_BF16(acc[t][2 * np + 1], aHi[t], bHi[2], bHi[3]);
                MMA_BF16(acc[t][2 * np],     aHi[t], bLo[0], bLo[1]);
                MMA_BF16(acc[t][2 * np + 1], aHi[t], bLo[2], bLo[3]);
                MMA_BF16(acc[t][2 * np],     aLo[t], bHi[0], bHi[1]);
                MMA_BF16(acc[t][2 * np + 1], aLo[t], bHi[2], bHi[3]);
            }
        }
    }

    // epilogue: fragment c0,c1 -> (row = lane>>2, cols 2(lane&3)+{0,1}); c2,c3 -> row+8
#pragma unroll
    for (int t = 0; t < 2; t++) {
        const int rbase = bm + wm * 32 + t * 16 + (lane >> 2);
#pragma unroll
        for (int ni = 0; ni < 8; ni++) {
            const int col = bn + wn * 64 + ni * 8 + (lane & 3) * 2;
            float bx = 0.0f, by = 0.0f;
            if (EPI != HEPI_ACC) { bx = bias[col]; by = bias[col + 1]; }
#pragma unroll
            for (int h = 0; h < 2; h++) {
                const int row = rbase + h * 8;
                float x = acc[t][ni][2 * h]     + bx;
                float y = acc[t][ni][2 * h + 1] + by;
                float* cp = C + (size_t)row * N + col;
                if (EPI == HEPI_BIAS) {
                    *(float2*)cp = make_float2(x, y);
                } else if (EPI == HEPI_ELU) {
                    *(float2*)cp = make_float2(elu_f(x), elu_f(y));
                } else if (EPI == HEPI_ELU_MASK_SPLIT) {
                    const float mk = rowvec[row];
                    x = elu_f(x) * mk; y = elu_f(y) * mk;
                    *(float2*)cp = make_float2(x, y);
                    const __nv_bfloat16 xh = __float2bfloat16(x);
                    const __nv_bfloat16 yh = __float2bfloat16(y);
                    __nv_bfloat162 vh; vh.x = xh; vh.y = yh;
                    __nv_bfloat162 vl;
                    vl.x = __float2bfloat16(x - __bfloat162float(xh));
                    vl.y = __float2bfloat16(y - __bfloat162float(yh));
                    *(__nv_bfloat162*)(Chi + (size_t)row * HDIM + col) = vh;
                    *(__nv_bfloat162*)(Clo + (size_t)row * HDIM + col) = vl;
                } else if (EPI == HEPI_ACC) {
                    float2 old = *(float2*)cp;
                    *(float2*)cp = make_float2(old.x + x - bx, old.y + y - by);
                } else if (EPI == HEPI_ELU_MUL) {
                    float2 old = *(float2*)cp;
                    *(float2*)cp = make_float2(old.x * elu_f(x), old.y * elu_f(y));
                }
            }
        }
    }
}

// ---------------- fused attention ----------------
__global__ void attn_kernel() {
    const int i = blockIdx.x;
    const int b = blockIdx.y;
    const int tid = threadIdx.x;
    const int lane = tid & 31;
    const int warp = tid >> 5;
    const int r = b * SL + i;

    __shared__ float sh_head[HDIM];
    __shared__ float sp[SL];
    __shared__ float rbuf[256];

    for (int k = tid; k < HDIM; k += 256) sh_head[k] = g_head[(size_t)r * HDIM + k];
    for (int j = tid; j < SL; j += 256) sp[j] = -3e38f;
    __syncthreads();

    for (int j = warp; j < i; j += 8) {
        const float* tr = g_tail + (size_t)(b * SL + j) * HDIM;
        float s = 0.0f;
        for (int k = lane; k < HDIM; k += 32) s = fmaf(sh_head[k], tr[k], s);
#pragma unroll
        for (int o = 16; o > 0; o >>= 1) s += __shfl_xor_sync(0xffffffff, s, o);
        if (lane == 0 && g_rowmask[b * SL + j] > 0.5f) sp[j] = s;
    }
    __syncthreads();

    float v = (tid < SL) ? sp[tid] : -3e38f;
    rbuf[tid] = v;
    __syncthreads();
    for (int s = 128; s > 0; s >>= 1) {
        if (tid < s) rbuf[tid] = fmaxf(rbuf[tid], rbuf[tid + s]);
        __syncthreads();
    }
    const float m = rbuf[0];
    __syncthreads();
    float e = 0.0f;
    if (tid < SL && sp[tid] > -1e37f) e = expf(sp[tid] - m);
    rbuf[tid] = e;
    __syncthreads();
    for (int s = 128; s > 0; s >>= 1) {
        if (tid < s) rbuf[tid] += rbuf[tid + s];
        __syncthreads();
    }
    const float ssum = rbuf[0];
    __syncthreads();
    if (tid < SL) sp[tid] = (ssum > 0.0f) ? e / ssum : 0.0f;
    __syncthreads();

    float a0 = 0.0f, a1 = 0.0f;
    for (int j = 0; j < i; j++) {
        const float s = sp[j];
        if (s != 0.0f) {
            const float* hr = g_hidden + (size_t)(b * SL + j) * HDIM;
            a0 = fmaf(s, hr[tid], a0);
            a1 = fmaf(s, hr[tid + 256], a1);
        }
    }
    g_depend[(size_t)r * HDIM + tid]       = a0;
    g_depend[(size_t)r * HDIM + tid + 256] = a1;
}

// ---------------- gate blend (fused split output) ----------------
__global__ void enc_kernel() {
    const int idx = blockIdx.x * 256 + threadIdx.x;
    const int r = idx >> 9;
    const float g = 1.0f / (1.0f + expf(-g_gbuf[idx]));
    const float x = (g * g_hidden[idx] + (1.0f - g) * g_depend[idx]) * g_rowmask[r];
    g_enc[idx] = x;
    const __nv_bfloat16 h = __float2bfloat16(x);
    g_encHi[idx] = h;
    g_encLo[idx] = __float2bfloat16(x - __bfloat162float(h));
}

// ---------------- map2 + pool softmax ----------------
__global__ void pool_kernel(const float* __restrict__ wm2, const float* __restrict__ bm2) {
    const int b = blockIdx.x;
    const int tid = threadIdx.x;
    const int lane = tid & 31;
    const int warp = tid >> 5;

    __shared__ float sm2[SL];
    __shared__ float rbuf[256];

    for (int i = warp; i < SL; i += 8) {
        const float* mr = g_m1 + (size_t)(b * SL + i) * HDIM;
        float s = 0.0f;
        for (int k = lane; k < HDIM; k += 32) s = fmaf(mr[k], wm2[k], s);
#pragma unroll
        for (int o = 16; o > 0; o >>= 1) s += __shfl_xor_sync(0xffffffff, s, o);
        if (lane == 0) sm2[i] = s + bm2[0];
    }
    __syncthreads();

    const bool valid = (tid < SL) && (g_rowmask[b * SL + tid] > 0.5f);
    float v = valid ? sm2[tid] : -3e38f;
    rbuf[tid] = v;
    __syncthreads();
    for (int s = 128; s > 0; s >>= 1) {
        if (tid < s) rbuf[tid] = fmaxf(rbuf[tid], rbuf[tid + s]);
        __syncthreads();
    }
    const float m = rbuf[0];
    __syncthreads();
    float e = valid ? expf(sm2[tid] - m) : 0.0f;
    rbuf[tid] = e;
    __syncthreads();
    for (int s = 128; s > 0; s >>= 1) {
        if (tid < s) rbuf[tid] += rbuf[tid + s];
        __syncthreads();
    }
    const float ssum = rbuf[0];
    if (tid < SL) g_pool[b * SL + tid] = (ssum > 0.0f) ? e / ssum : 0.0f;
}

// A = (pool * enc) -> bf16 hi/lo
__global__ void convA_kernel() {
    const int idx = blockIdx.x * 256 + threadIdx.x;
    const int row = idx >> 9;
    const float x = g_enc[idx] * g_pool[row];
    const __nv_bfloat16 hi = __float2bfloat16(x);
    g_Ahi[idx] = hi;
    g_Alo[idx] = __float2bfloat16(x - __bfloat162float(hi));
}

// ---------------- launch ----------------
extern "C" void kernel_launch(void* const* d_in, const int* in_sizes, int n_in,
                              void* d_out, int out_size) {
    const int*   cas  = (const int*)d_in[0];
    const int*   tiiv = (const int*)d_in[1];
    const float* emb  = (const float*)d_in[2];
    const float* tl   = (const float*)d_in[3];
    const float* w1   = (const float*)d_in[4];
    const float* b1   = (const float*)d_in[5];
    const float* wh   = (const float*)d_in[6];
    const float* bh   = (const float*)d_in[7];
    const float* wt   = (const float*)d_in[8];
    const float* bt   = (const float*)d_in[9];
    const float* wg   = (const float*)d_in[10];
    const float* bg   = (const float*)d_in[11];
    const float* wm1  = (const float*)d_in[12];
    const float* bm1  = (const float*)d_in[13];
    const float* wti  = (const float*)d_in[14];
    const float* bti  = (const float*)d_in[15];
    const float* wm2  = (const float*)d_in[16];
    const float* bm2  = (const float*)d_in[17];
    const float* wout = (const float*)d_in[18];
    const float* bout = (const float*)d_in[19];
    float* out = (float*)d_out;

    float *hiddenP, *headP, *tailP, *dependP, *gbufP, *encP, *m1P, *rowmaskP, *poolP;
    int *gidxP, *tidxP;
    __nv_bfloat16 *embHiP, *embLoP, *tlHiP, *tlLoP, *hidHiP, *hidLoP, *depHiP, *depLoP;
    __nv_bfloat16 *encHiP, *encLoP, *AhiP, *AloP, *BhiP, *BloP, *wTHiP, *wTLoP;
    cudaGetSymbolAddress((void**)&hiddenP, g_hidden);
    cudaGetSymbolAddress((void**)&headP,   g_head);
    cudaGetSymbolAddress((void**)&tailP,   g_tail);
    cudaGetSymbolAddress((void**)&dependP, g_depend);
    cudaGetSymbolAddress((void**)&gbufP,   g_gbuf);
    cudaGetSymbolAddress((void**)&encP,    g_enc);
    cudaGetSymbolAddress((void**)&m1P,     g_m1);
    cudaGetSymbolAddress((void**)&rowmaskP,g_rowmask);
    cudaGetSymbolAddress((void**)&poolP,   g_pool);
    cudaGetSymbolAddress((void**)&gidxP,   g_gidx);
    cudaGetSymbolAddress((void**)&tidxP,   g_tidx);
    cudaGetSymbolAddress((void**)&embHiP,  g_embHi);
    cudaGetSymbolAddress((void**)&embLoP,  g_embLo);
    cudaGetSymbolAddress((void**)&tlHiP,   g_tlHi);
    cudaGetSymbolAddress((void**)&tlLoP,   g_tlLo);
    cudaGetSymbolAddress((void**)&hidHiP,  g_hidHi);
    cudaGetSymbolAddress((void**)&hidLoP,  g_hidLo);
    cudaGetSymbolAddress((void**)&depHiP,  g_depHi);
    cudaGetSymbolAddress((void**)&depLoP,  g_depLo);
    cudaGetSymbolAddress((void**)&encHiP,  g_encHi);
    cudaGetSymbolAddress((void**)&encLoP,  g_encLo);
    cudaGetSymbolAddress((void**)&AhiP,    g_Ahi);
    cudaGetSymbolAddress((void**)&AloP,    g_Alo);
    cudaGetSymbolAddress((void**)&BhiP,    g_Bhi);
    cudaGetSymbolAddress((void**)&BloP,    g_Blo);
    cudaGetSymbolAddress((void**)&wTHiP,   g_wTHi);
    cudaGetSymbolAddress((void**)&wTLoP,   g_wTLo);

    prep_kernel<<<BBATCH, 256>>>(cas, tiiv);

    // operand prep: split emb + time_lambda; transpose+split weights (+wout)
    split_kernel<<<(VDIM * EDIM) / 256, 256>>>(emb, embHiP, embLoP, VDIM * EDIM);
    split_kernel<<<(TDIM * HDIM + 255) / 256, 256>>>(tl, tlHiP, tlLoP, TDIM * HDIM);
    dim3 cT(16, 16), cB(32, 8);
    convT_kernel<<<cT, cB>>>(w1,  HDIM, wTHiP + 0 * WSLOT, wTLoP + 0 * WSLOT);
    convT_kernel<<<cT, cB>>>(wh,  HDIM, wTHiP + 1 * WSLOT, wTLoP + 1 * WSLOT);
    convT_kernel<<<cT, cB>>>(wt,  HDIM, wTHiP + 2 * WSLOT, wTLoP + 2 * WSLOT);
    convT_kernel<<<cT, cB>>>(wg,  HDIM, wTHiP + 3 * WSLOT, wTLoP + 3 * WSLOT);
    convT_kernel<<<cT, cB>>>(wg + (size_t)HDIM * HDIM, HDIM,
                             wTHiP + 4 * WSLOT, wTLoP + 4 * WSLOT);
    convT_kernel<<<cT, cB>>>(wm1, HDIM, wTHiP + 5 * WSLOT, wTLoP + 5 * WSLOT);
    convT_kernel<<<cT, cB>>>(wti, HDIM, wTHiP + 6 * WSLOT, wTLoP + 6 * WSLOT);
    convT_kernel<<<dim3(VDIM / 32, 16), cB>>>(wout, VDIM, BhiP, BloP);

    dim3 gH(HDIM / 128, MROWS / 128);   // (4, 50)
    dim3 gV(VDIM / 128, MROWS / 128);   // (250, 50)

    // hidden = elu(gather(emb) @ w1 + b1) * rowmask  (+ fused split)
    hmma_gemm<HEPI_ELU_MASK_SPLIT, true><<<gH, 256>>>(
        embHiP, embLoP, wTHiP + 0 * WSLOT, wTLoP + 0 * WSLOT,
        hiddenP, b1, gidxP, rowmaskP, hidHiP, hidLoP, HDIM);
    // head / tail
    hmma_gemm<HEPI_BIAS, false><<<gH, 256>>>(
        hidHiP, hidLoP, wTHiP + 1 * WSLOT, wTLoP + 1 * WSLOT,
        headP, bh, nullptr, nullptr, nullptr, nullptr, HDIM);
    hmma_gemm<HEPI_BIAS, false><<<gH, 256>>>(
        hidHiP, hidLoP, wTHiP + 2 * WSLOT, wTLoP + 2 * WSLOT,
        tailP, bt, nullptr, nullptr, nullptr, nullptr, HDIM);

    // attention -> depend, then split depend
    attn_kernel<<<dim3(SL, BBATCH), 256>>>();
    split_kernel<<<(MROWS * HDIM) / 256, 256>>>(dependP, depHiP, depLoP, MROWS * HDIM);

    // gate pre-activation
    hmma_gemm<HEPI_BIAS, false><<<gH, 256>>>(
        hidHiP, hidLoP, wTHiP + 3 * WSLOT, wTLoP + 3 * WSLOT,
        gbufP, bg, nullptr, nullptr, nullptr, nullptr, HDIM);
    hmma_gemm<HEPI_ACC, false><<<gH, 256>>>(
        depHiP, depLoP, wTHiP + 4 * WSLOT, wTLoP + 4 * WSLOT,
        gbufP, nullptr, nullptr, nullptr, nullptr, nullptr, HDIM);

    // enc blend (+ fused split)
    enc_kernel<<<(MROWS * HDIM) / 256, 256>>>();

    // m1 = elu(enc@wm1 + bm1); m1 *= elu(gather(time_lambda)@wti + bti)
    hmma_gemm<HEPI_ELU, false><<<gH, 256>>>(
        encHiP, encLoP, wTHiP + 5 * WSLOT, wTLoP + 5 * WSLOT,
        m1P, bm1, nullptr, nullptr, nullptr, nullptr, HDIM);
    hmma_gemm<HEPI_ELU_MUL, true><<<gH, 256>>>(
        tlHiP, tlLoP, wTHiP + 6 * WSLOT, wTLoP + 6 * WSLOT,
        m1P, bti, tidxP, nullptr, nullptr, nullptr, HDIM);

    // pool softmax over sequence
    pool_kernel<<<BBATCH, 256>>>(wm2, bm2);

    // A = pool*enc -> bf16 hi/lo
    convA_kernel<<<(MROWS * HDIM) / 256, 256>>>();

    // logits_out = A @ wout^T + bout
    hmma_gemm<HEPI_BIAS, false><<<gV, 256>>>(
        AhiP, AloP, BhiP, BloP, out, bout, nullptr, nullptr, nullptr, nullptr, VDIM);
}